// round 1
// baseline (speedup 1.0000x reference)
#include <cuda_runtime.h>
#include <math.h>

#define HW    16384
#define WIDTH 128
#define NB    8
#define CQKV  192

// ---------------- scratch (static device allocations; no cudaMalloc) --------
__device__ float g_qkv[NB * CQKV * HW];   // 100.7 MB
__device__ float g_p  [NB * CQKV * HW];   // 100.7 MB
__device__ float g_d  [NB * CQKV * HW];   // 100.7 MB
__device__ float g_o  [NB * 128  * HW];   //  67.1 MB
__device__ float g_kvp[NB * 16 * 8 * 72]; // per-chunk partial kv sums
__device__ float g_kv [NB * 16 * 72];     // reduced kv

// ---------------- generic fp32 tiled GEMM: C[b] = A (MxK) * B[b] (KxN) ------
// Row stride of B and C is N (true for all uses here: N == HW).
// EPI==1 applies batchnorm affine per output row m.
template <int EPI>
__global__ void sgemm_kernel(const float* __restrict__ A,
                             const float* __restrict__ B,
                             float* __restrict__ C,
                             int M, int N, int K,
                             size_t bStrideB, size_t bStrideC,
                             const float* __restrict__ gamma,
                             const float* __restrict__ beta,
                             const float* __restrict__ mean,
                             const float* __restrict__ var)
{
    constexpr int BM = 64, BN = 64, BK = 32;
    __shared__ float As[BK][BM + 1];
    __shared__ float Bs[BK][BN];

    const float* Bb = B + bStrideB * blockIdx.z;
    float*       Cb = C + bStrideC * blockIdx.z;
    const int m0 = blockIdx.y * BM;
    const int n0 = blockIdx.x * BN;
    const int tid = threadIdx.x;
    const int tx = tid & 15;       // 16 threads over N
    const int ty = tid >> 4;       // 16 threads over M

    float acc[4][4] = {};

    for (int k0 = 0; k0 < K; k0 += BK) {
        // A tile: 64 rows x 32 k, coalesced over k, stored transposed (padded)
        #pragma unroll
        for (int i = tid; i < BM * BK; i += 256) {
            int m = i >> 5, k = i & 31;
            As[k][m] = A[(m0 + m) * K + k0 + k];
        }
        // B tile: 32 k-rows x 64 n, coalesced over n
        #pragma unroll
        for (int i = tid; i < BK * BN; i += 256) {
            int k = i >> 6, n = i & 63;
            Bs[k][n] = Bb[(size_t)(k0 + k) * N + n0 + n];
        }
        __syncthreads();

        #pragma unroll
        for (int k = 0; k < BK; k++) {
            float a[4], bb[4];
            #pragma unroll
            for (int j = 0; j < 4; j++) { a[j] = As[k][ty * 4 + j]; bb[j] = Bs[k][tx * 4 + j]; }
            #pragma unroll
            for (int i = 0; i < 4; i++)
                #pragma unroll
                for (int j = 0; j < 4; j++)
                    acc[i][j] += a[i] * bb[j];
        }
        __syncthreads();
    }

    #pragma unroll
    for (int i = 0; i < 4; i++) {
        int m = m0 + ty * 4 + i;
        float sc = 1.f, sh = 0.f;
        if (EPI) {
            sc = gamma[m] * rsqrtf(var[m] + 1e-5f);
            sh = beta[m] - mean[m] * sc;
        }
        #pragma unroll
        for (int j = 0; j < 4; j++)
            Cb[(size_t)m * N + n0 + tx * 4 + j] = acc[i][j] * sc + sh;
    }
}

// ---------------- p = blockdiag(W_p) applied to qkv (pointwise per pixel) ---
__global__ void p_kernel(const float* __restrict__ QKV,
                         const float* __restrict__ Wp,
                         float* __restrict__ P)
{
    __shared__ float wp[24 * 64];
    for (int i = threadIdx.x; i < 24 * 64; i += 256) wp[i] = Wp[i];
    __syncthreads();

    const int b = blockIdx.y;
    const int n = blockIdx.x * 256 + threadIdx.x;
    const float* src = QKV + (size_t)b * CQKV * HW + n;
    float*       dst = P   + (size_t)b * CQKV * HW + n;

    #pragma unroll
    for (int g = 0; g < 24; g++) {
        float in[8];
        #pragma unroll
        for (int i = 0; i < 8; i++) in[i] = src[(g * 8 + i) * HW];
        #pragma unroll
        for (int o = 0; o < 8; o++) {
            float s = 0.f;
            #pragma unroll
            for (int i = 0; i < 8; i++) s += wp[g * 64 + o * 8 + i] * in[i];
            dst[(g * 8 + o) * HW] = s;
        }
    }
}

// ---------------- depthwise 3x3, SAME padding (cross-correlation) -----------
__global__ void dw_kernel(const float* __restrict__ P,
                          const float* __restrict__ Wd,
                          float* __restrict__ D)
{
    const int b = blockIdx.z, c = blockIdx.y;
    const int n = blockIdx.x * 256 + threadIdx.x;
    const int h = n >> 7, w = n & 127;
    const float* src = P + ((size_t)b * CQKV + c) * HW;

    float wreg[9];
    #pragma unroll
    for (int i = 0; i < 9; i++) wreg[i] = Wd[c * 9 + i];

    float s = 0.f;
    #pragma unroll
    for (int ky = 0; ky < 3; ky++) {
        int y = h + ky - 1;
        if ((unsigned)y >= (unsigned)WIDTH) continue;
        #pragma unroll
        for (int kx = 0; kx < 3; kx++) {
            int x2 = w + kx - 1;
            if ((unsigned)x2 >= (unsigned)WIDTH) continue;
            s += wreg[ky * 3 + kx] * src[y * WIDTH + x2];
        }
    }
    D[((size_t)b * CQKV + c) * HW + n] = s;
}

// ---------------- kv partial sums: kv[b,G] = sum_n relu(k) outer [v|1] ------
// grid: (8 chunks, 16 groups, 8 batches); each thread covers 8 pixels
__global__ void kv_kernel(const float* __restrict__ QKV,
                          const float* __restrict__ D,
                          float* __restrict__ kvp)
{
    const int b = blockIdx.z, G = blockIdx.y, chunk = blockIdx.x;
    const int tid = threadIdx.x;
    const float* base = (G < 8) ? QKV + ((size_t)b * CQKV + G * 24) * HW
                                : D   + ((size_t)b * CQKV + (G - 8) * 24) * HW;
    float acc[72];
    #pragma unroll
    for (int i = 0; i < 72; i++) acc[i] = 0.f;

    for (int it = 0; it < 8; it++) {
        int n = chunk * 2048 + it * 256 + tid;
        float kr[8], vr[8];
        #pragma unroll
        for (int d = 0; d < 8; d++) kr[d] = fmaxf(base[(8 + d) * HW + n], 0.f);
        #pragma unroll
        for (int e = 0; e < 8; e++) vr[e] = base[(16 + e) * HW + n];
        #pragma unroll
        for (int d = 0; d < 8; d++) {
            #pragma unroll
            for (int e = 0; e < 8; e++) acc[d * 9 + e] += kr[d] * vr[e];
            acc[d * 9 + 8] += kr[d];
        }
    }

    __shared__ float red[8][72];
    const int lane = tid & 31, warp = tid >> 5;
    #pragma unroll
    for (int i = 0; i < 72; i++) {
        float v = acc[i];
        #pragma unroll
        for (int off = 16; off; off >>= 1) v += __shfl_down_sync(0xffffffffu, v, off);
        if (lane == 0) red[warp][i] = v;
    }
    __syncthreads();
    for (int i = tid; i < 72; i += 256) {
        float s = 0.f;
        #pragma unroll
        for (int w2 = 0; w2 < 8; w2++) s += red[w2][i];
        kvp[((size_t)(b * 16 + G) * 8 + chunk) * 72 + i] = s;
    }
}

// deterministic second-stage reduce: 9216 values, 8 chunk partials each
__global__ void kv_reduce(const float* __restrict__ kvp, float* __restrict__ kv)
{
    int i = blockIdx.x * 256 + threadIdx.x;       // < 8*16*72 = 9216
    int bg = i / 72, j = i % 72;
    float s = 0.f;
    #pragma unroll
    for (int c = 0; c < 8; c++) s += kvp[((size_t)bg * 8 + c) * 72 + j];
    kv[i] = s;
}

// ---------------- o = normalize(relu(q) @ kv), stored channel-major ---------
__global__ void o_kernel(const float* __restrict__ QKV,
                         const float* __restrict__ D,
                         const float* __restrict__ kv,
                         float* __restrict__ O)
{
    const int b = blockIdx.y;
    __shared__ float skv[16 * 72];
    for (int i = threadIdx.x; i < 16 * 72; i += 256) skv[i] = kv[b * 16 * 72 + i];
    __syncthreads();

    const int n = blockIdx.x * 256 + threadIdx.x;
    #pragma unroll
    for (int G = 0; G < 16; G++) {
        const float* base = (G < 8) ? QKV + ((size_t)b * CQKV + G * 24) * HW
                                    : D   + ((size_t)b * CQKV + (G - 8) * 24) * HW;
        float num[8] = {};
        float den = 0.f;
        #pragma unroll
        for (int d = 0; d < 8; d++) {
            float q = fmaxf(base[d * HW + n], 0.f);
            #pragma unroll
            for (int j = 0; j < 8; j++) num[j] += q * skv[G * 72 + d * 9 + j];
            den += q * skv[G * 72 + d * 9 + 8];
        }
        float inv = 1.f / (den + 1e-15f);
        #pragma unroll
        for (int j = 0; j < 8; j++)
            O[((size_t)b * 128 + G * 8 + j) * HW + n] = num[j] * inv;
    }
}

// ---------------- launch --------------------------------------------------
extern "C" void kernel_launch(void* const* d_in, const int* in_sizes, int n_in,
                              void* d_out, int out_size)
{
    const float* x     = (const float*)d_in[0];
    const float* W_qkv = (const float*)d_in[1];
    const float* W_p   = (const float*)d_in[2];
    const float* W_d   = (const float*)d_in[3];
    const float* W_ffn = (const float*)d_in[4];
    const float* gamma = (const float*)d_in[5];
    const float* beta  = (const float*)d_in[6];
    const float* mean  = (const float*)d_in[7];
    const float* var   = (const float*)d_in[8];
    float* out = (float*)d_out;

    float *qkv, *p, *d, *o, *kvp, *kv;
    cudaGetSymbolAddress((void**)&qkv, g_qkv);
    cudaGetSymbolAddress((void**)&p,   g_p);
    cudaGetSymbolAddress((void**)&d,   g_d);
    cudaGetSymbolAddress((void**)&o,   g_o);
    cudaGetSymbolAddress((void**)&kvp, g_kvp);
    cudaGetSymbolAddress((void**)&kv,  g_kv);

    // 1) qkv = W_qkv @ x           (192x256)(256x16384) per batch
    sgemm_kernel<0><<<dim3(HW / 64, CQKV / 64, NB), 256>>>(
        W_qkv, x, qkv, CQKV, HW, 256,
        (size_t)256 * HW, (size_t)CQKV * HW, nullptr, nullptr, nullptr, nullptr);

    // 2) p = blockdiag(W_p) @ qkv  (pointwise)
    p_kernel<<<dim3(HW / 256, NB), 256>>>(qkv, W_p, p);

    // 3) d = depthwise3x3(p)
    dw_kernel<<<dim3(HW / 256, CQKV, NB), 256>>>(p, W_d, d);

    // 4) kv reduction (two-stage, deterministic)
    kv_kernel<<<dim3(8, 16, NB), 256>>>(qkv, d, kvp);
    kv_reduce<<<(NB * 16 * 72) / 256, 256>>>(kvp, kv);

    // 5) o = normalize(relu(q) @ kv)
    o_kernel<<<dim3(HW / 256, NB), 256>>>(qkv, d, kv, o);

    // 6) out = BN(W_ffn @ o)       (256x128)(128x16384) per batch
    sgemm_kernel<1><<<dim3(HW / 64, 256 / 64, NB), 256>>>(
        W_ffn, o, out, 256, HW, 128,
        (size_t)128 * HW, (size_t)256 * HW, gamma, beta, mean, var);
}

// round 2
// speedup vs baseline: 1.8830x; 1.8830x over previous
#include <cuda_runtime.h>
#include <math.h>
#include <stdint.h>

#define HW    16384
#define WIDTH 128
#define NB    8
#define CQKV  192

// ---------------- scratch (static device allocations; no cudaMalloc) --------
__device__ float g_qkv[NB * CQKV * HW];   // 100.7 MB
__device__ float g_p  [NB * CQKV * HW];   // 100.7 MB
__device__ float g_d  [NB * CQKV * HW];   // 100.7 MB
__device__ float g_o  [NB * 128  * HW];   //  67.1 MB
__device__ float g_kvp[NB * 16 * 8 * 72]; // per-chunk partial kv sums
__device__ float g_kv [NB * 16 * 72];     // reduced kv

// ---------------- TF32 helpers ---------------------------------------------
__device__ __forceinline__ uint32_t tf32_hi(float x) {
    // round-to-nearest to tf32 (10-bit mantissa), result has low 13 bits zero
    uint32_t u = __float_as_uint(x);
    return (u + 0x1000u) & 0xFFFFE000u;
}

__device__ __forceinline__ void mma_tf32(float c[4], const uint32_t a[4], const uint32_t b[2]) {
    asm volatile(
        "mma.sync.aligned.m16n8k8.row.col.f32.tf32.tf32.f32 "
        "{%0,%1,%2,%3}, {%4,%5,%6,%7}, {%8,%9}, {%0,%1,%2,%3};\n"
        : "+f"(c[0]), "+f"(c[1]), "+f"(c[2]), "+f"(c[3])
        : "r"(a[0]), "r"(a[1]), "r"(a[2]), "r"(a[3]), "r"(b[0]), "r"(b[1]));
}

// ---------------- TF32x3 tensor-core GEMM: C[b] = A (MxK) * B[b] (KxN) ------
// Block tile 64x64, BK=32, 128 threads (4 warps, each 32x32 via m16n8k8).
// MODE 0: plain store.  MODE 1: batchnorm affine.  MODE 2: store C and the
// per-group 8x8 mix P = blockdiag(W_p) * C.
// Requires M%64==0, N%64==0, K%32==0 (true for all uses).
template <int MODE>
__global__ void __launch_bounds__(128)
tgemm_kernel(const float* __restrict__ A,
             const float* __restrict__ B,
             float* __restrict__ C,
             int M, int N, int K,
             size_t bStrideB, size_t bStrideC,
             float* __restrict__ Pout,
             const float* __restrict__ Wp,
             const float* __restrict__ gamma,
             const float* __restrict__ beta,
             const float* __restrict__ mean,
             const float* __restrict__ var)
{
    __shared__ float smem[4608];          // 18 KB
    float* As = smem;                      // [64][36]  (padded)
    float* Bs = smem + 64 * 36;            // [32][72]  (padded)
    float* Cs = smem;                      // [64][68]  (reused after mainloop)

    const int tid  = threadIdx.x;
    const int lane = tid & 31;
    const int warp = tid >> 5;
    const int wm   = warp >> 1;            // warp row (0..1) -> 32 rows
    const int wn   = warp & 1;             // warp col (0..1) -> 32 cols
    const int g    = lane >> 2;            // octet id 0..7
    const int tg   = lane & 3;             // thread-in-group 0..3

    const int m0 = blockIdx.y * 64;
    const int n0 = blockIdx.x * 64;
    const float* Bb = B + bStrideB * blockIdx.z;
    float*       Cb = C + bStrideC * blockIdx.z;

    float c[2][4][4] = {};

    for (int kt = 0; kt < K; kt += 32) {
        // A tile: 64x32, float4 loads, padded stride 36
        #pragma unroll
        for (int j = 0; j < 4; j++) {
            int lin = (tid + j * 128) * 4;
            int m = lin >> 5, k = lin & 31;
            float4 v = *(const float4*)&A[(size_t)(m0 + m) * K + kt + k];
            *(float4*)&As[m * 36 + k] = v;
        }
        // B tile: 32x64, float4 loads, padded stride 72
        #pragma unroll
        for (int j = 0; j < 4; j++) {
            int lin = (tid + j * 128) * 4;
            int k = lin >> 6, n = lin & 63;
            float4 v = *(const float4*)&Bb[(size_t)(kt + k) * N + n0 + n];
            *(float4*)&Bs[k * 72 + n] = v;
        }
        __syncthreads();

        #pragma unroll
        for (int ks = 0; ks < 32; ks += 8) {
            uint32_t ah[2][4], al[2][4], bh[4][2], bl[4][2];
            #pragma unroll
            for (int mt = 0; mt < 2; mt++) {
                int br = wm * 32 + mt * 16;
                float a0 = As[(br + g)     * 36 + ks + tg];
                float a1 = As[(br + g + 8) * 36 + ks + tg];
                float a2 = As[(br + g)     * 36 + ks + tg + 4];
                float a3 = As[(br + g + 8) * 36 + ks + tg + 4];
                ah[mt][0] = tf32_hi(a0); al[mt][0] = __float_as_uint(a0 - __uint_as_float(ah[mt][0]));
                ah[mt][1] = tf32_hi(a1); al[mt][1] = __float_as_uint(a1 - __uint_as_float(ah[mt][1]));
                ah[mt][2] = tf32_hi(a2); al[mt][2] = __float_as_uint(a2 - __uint_as_float(ah[mt][2]));
                ah[mt][3] = tf32_hi(a3); al[mt][3] = __float_as_uint(a3 - __uint_as_float(ah[mt][3]));
            }
            #pragma unroll
            for (int nt = 0; nt < 4; nt++) {
                int col = wn * 32 + nt * 8 + g;
                float b0 = Bs[(ks + tg)     * 72 + col];
                float b1 = Bs[(ks + tg + 4) * 72 + col];
                bh[nt][0] = tf32_hi(b0); bl[nt][0] = __float_as_uint(b0 - __uint_as_float(bh[nt][0]));
                bh[nt][1] = tf32_hi(b1); bl[nt][1] = __float_as_uint(b1 - __uint_as_float(bh[nt][1]));
            }
            #pragma unroll
            for (int mt = 0; mt < 2; mt++)
                #pragma unroll
                for (int nt = 0; nt < 4; nt++) {
                    mma_tf32(c[mt][nt], ah[mt], bh[nt]);   // hi*hi
                    mma_tf32(c[mt][nt], ah[mt], bl[nt]);   // hi*lo
                    mma_tf32(c[mt][nt], al[mt], bh[nt]);   // lo*hi
                }
        }
        __syncthreads();
    }

    // ---- stage C tile to shared (stride 68) ----
    #pragma unroll
    for (int mt = 0; mt < 2; mt++)
        #pragma unroll
        for (int nt = 0; nt < 4; nt++) {
            int r   = wm * 32 + mt * 16 + g;
            int col = wn * 32 + nt * 8 + tg * 2;
            Cs[r * 68 + col]           = c[mt][nt][0];
            Cs[r * 68 + col + 1]       = c[mt][nt][1];
            Cs[(r + 8) * 68 + col]     = c[mt][nt][2];
            Cs[(r + 8) * 68 + col + 1] = c[mt][nt][3];
        }
    __syncthreads();

    // ---- write out ----
    #pragma unroll 8
    for (int i = tid; i < 4096; i += 128) {
        int r = i >> 6, n = i & 63;
        float v = Cs[r * 68 + n];
        if (MODE == 1) {
            int m = m0 + r;
            float sc = gamma[m] * rsqrtf(var[m] + 1e-5f);
            v = v * sc + beta[m] - mean[m] * sc;
        }
        Cb[(size_t)(m0 + r) * N + n0 + n] = v;
    }

    if (MODE == 2) {
        // per-group 8x8 mix: P[g*8+o] = sum_i Wp[g][o][i] * C[g*8+i]
        float* Pb = Pout + bStrideC * blockIdx.z;
        const int pix  = tid & 63;
        const int half = tid >> 6;
        #pragma unroll
        for (int gl = 0; gl < 4; gl++) {
            int g_loc  = half * 4 + gl;          // 0..7 within the 64-row tile
            int g_glob = (m0 >> 3) + g_loc;
            float in[8];
            #pragma unroll
            for (int i = 0; i < 8; i++) in[i] = Cs[(g_loc * 8 + i) * 68 + pix];
            #pragma unroll
            for (int o = 0; o < 8; o++) {
                float s = 0.f;
                #pragma unroll
                for (int i = 0; i < 8; i++)
                    s += __ldg(&Wp[g_glob * 64 + o * 8 + i]) * in[i];
                Pb[(size_t)(m0 + g_loc * 8 + o) * N + n0 + pix] = s;
            }
        }
    }
}

// ---------------- depthwise 3x3, SAME padding (cross-correlation) -----------
__global__ void dw_kernel(const float* __restrict__ P,
                          const float* __restrict__ Wd,
                          float* __restrict__ D)
{
    const int b = blockIdx.z, c = blockIdx.y;
    const int n = blockIdx.x * 256 + threadIdx.x;
    const int h = n >> 7, w = n & 127;
    const float* src = P + ((size_t)b * CQKV + c) * HW;

    float wreg[9];
    #pragma unroll
    for (int i = 0; i < 9; i++) wreg[i] = Wd[c * 9 + i];

    float s = 0.f;
    #pragma unroll
    for (int ky = 0; ky < 3; ky++) {
        int y = h + ky - 1;
        if ((unsigned)y >= (unsigned)WIDTH) continue;
        #pragma unroll
        for (int kx = 0; kx < 3; kx++) {
            int x2 = w + kx - 1;
            if ((unsigned)x2 >= (unsigned)WIDTH) continue;
            s += wreg[ky * 3 + kx] * src[y * WIDTH + x2];
        }
    }
    D[((size_t)b * CQKV + c) * HW + n] = s;
}

// ---------------- kv partial sums: kv[b,G] = sum_n relu(k) outer [v|1] ------
__global__ void kv_kernel(const float* __restrict__ QKV,
                          const float* __restrict__ D,
                          float* __restrict__ kvp)
{
    const int b = blockIdx.z, G = blockIdx.y, chunk = blockIdx.x;
    const int tid = threadIdx.x;
    const float* base = (G < 8) ? QKV + ((size_t)b * CQKV + G * 24) * HW
                                : D   + ((size_t)b * CQKV + (G - 8) * 24) * HW;
    float acc[72];
    #pragma unroll
    for (int i = 0; i < 72; i++) acc[i] = 0.f;

    for (int it = 0; it < 8; it++) {
        int n = chunk * 2048 + it * 256 + tid;
        float kr[8], vr[8];
        #pragma unroll
        for (int d = 0; d < 8; d++) kr[d] = fmaxf(base[(8 + d) * HW + n], 0.f);
        #pragma unroll
        for (int e = 0; e < 8; e++) vr[e] = base[(16 + e) * HW + n];
        #pragma unroll
        for (int d = 0; d < 8; d++) {
            #pragma unroll
            for (int e = 0; e < 8; e++) acc[d * 9 + e] += kr[d] * vr[e];
            acc[d * 9 + 8] += kr[d];
        }
    }

    __shared__ float red[8][72];
    const int lane = tid & 31, warp = tid >> 5;
    #pragma unroll
    for (int i = 0; i < 72; i++) {
        float v = acc[i];
        #pragma unroll
        for (int off = 16; off; off >>= 1) v += __shfl_down_sync(0xffffffffu, v, off);
        if (lane == 0) red[warp][i] = v;
    }
    __syncthreads();
    for (int i = tid; i < 72; i += 256) {
        float s = 0.f;
        #pragma unroll
        for (int w2 = 0; w2 < 8; w2++) s += red[w2][i];
        kvp[((size_t)(b * 16 + G) * 8 + chunk) * 72 + i] = s;
    }
}

__global__ void kv_reduce(const float* __restrict__ kvp, float* __restrict__ kv)
{
    int i = blockIdx.x * 256 + threadIdx.x;       // < 8*16*72 = 9216
    int bg = i / 72, j = i % 72;
    float s = 0.f;
    #pragma unroll
    for (int c = 0; c < 8; c++) s += kvp[((size_t)bg * 8 + c) * 72 + j];
    kv[i] = s;
}

// ---------------- o = normalize(relu(q) @ kv), stored channel-major ---------
__global__ void o_kernel(const float* __restrict__ QKV,
                         const float* __restrict__ D,
                         const float* __restrict__ kv,
                         float* __restrict__ O)
{
    const int b = blockIdx.y;
    __shared__ float skv[16 * 72];
    for (int i = threadIdx.x; i < 16 * 72; i += 256) skv[i] = kv[b * 16 * 72 + i];
    __syncthreads();

    const int n = blockIdx.x * 256 + threadIdx.x;
    #pragma unroll
    for (int G = 0; G < 16; G++) {
        const float* base = (G < 8) ? QKV + ((size_t)b * CQKV + G * 24) * HW
                                    : D   + ((size_t)b * CQKV + (G - 8) * 24) * HW;
        float num[8] = {};
        float den = 0.f;
        #pragma unroll
        for (int d = 0; d < 8; d++) {
            float q = fmaxf(base[d * HW + n], 0.f);
            #pragma unroll
            for (int j = 0; j < 8; j++) num[j] += q * skv[G * 72 + d * 9 + j];
            den += q * skv[G * 72 + d * 9 + 8];
        }
        float inv = 1.f / (den + 1e-15f);
        #pragma unroll
        for (int j = 0; j < 8; j++)
            O[((size_t)b * 128 + G * 8 + j) * HW + n] = num[j] * inv;
    }
}

// ---------------- launch --------------------------------------------------
extern "C" void kernel_launch(void* const* d_in, const int* in_sizes, int n_in,
                              void* d_out, int out_size)
{
    const float* x     = (const float*)d_in[0];
    const float* W_qkv = (const float*)d_in[1];
    const float* W_p   = (const float*)d_in[2];
    const float* W_d   = (const float*)d_in[3];
    const float* W_ffn = (const float*)d_in[4];
    const float* gamma = (const float*)d_in[5];
    const float* beta  = (const float*)d_in[6];
    const float* mean  = (const float*)d_in[7];
    const float* var   = (const float*)d_in[8];
    float* out = (float*)d_out;

    float *qkv, *p, *d, *o, *kvp, *kv;
    cudaGetSymbolAddress((void**)&qkv, g_qkv);
    cudaGetSymbolAddress((void**)&p,   g_p);
    cudaGetSymbolAddress((void**)&d,   g_d);
    cudaGetSymbolAddress((void**)&o,   g_o);
    cudaGetSymbolAddress((void**)&kvp, g_kvp);
    cudaGetSymbolAddress((void**)&kv,  g_kv);

    // 1) qkv = W_qkv @ x  AND  p = blockdiag(W_p) @ qkv (fused epilogue)
    tgemm_kernel<2><<<dim3(HW / 64, CQKV / 64, NB), 128>>>(
        W_qkv, x, qkv, CQKV, HW, 256,
        (size_t)256 * HW, (size_t)CQKV * HW,
        p, W_p, nullptr, nullptr, nullptr, nullptr);

    // 2) d = depthwise3x3(p)
    dw_kernel<<<dim3(HW / 256, CQKV, NB), 256>>>(p, W_d, d);

    // 3) kv reduction (two-stage, deterministic)
    kv_kernel<<<dim3(8, 16, NB), 256>>>(qkv, d, kvp);
    kv_reduce<<<(NB * 16 * 72) / 256, 256>>>(kvp, kv);

    // 4) o = normalize(relu(q) @ kv)
    o_kernel<<<dim3(HW / 256, NB), 256>>>(qkv, d, kv, o);

    // 5) out = BN(W_ffn @ o)
    tgemm_kernel<1><<<dim3(HW / 64, 256 / 64, NB), 128>>>(
        W_ffn, o, out, 256, HW, 128,
        (size_t)128 * HW, (size_t)256 * HW,
        nullptr, nullptr, gamma, beta, mean, var);
}

// round 3
// speedup vs baseline: 1.8847x; 1.0009x over previous
#include <cuda_runtime.h>
#include <cuda_bf16.h>
#include <math.h>
#include <stdint.h>

#define HW    16384
#define WIDTH 128
#define NB    8
#define CQKV  192

// ---------------- scratch (static device allocations; no cudaMalloc) --------
__device__ float g_qkv[NB * CQKV * HW];   // 100.7 MB
__device__ float g_d  [NB * CQKV * HW];   // 100.7 MB
__device__ float g_o  [NB * 128  * HW];   //  67.1 MB
__device__ float g_kvp[NB * 16 * 8 * 72]; // per-chunk partial kv sums
__device__ float g_kv [NB * 16 * 72];     // reduced kv

// ---------------- bf16 split helpers ----------------------------------------
__device__ __forceinline__ void bsplit(float x, float& h, float& l) {
    h = __bfloat162float(__float2bfloat16_rn(x));
    l = x - h;
}
__device__ __forceinline__ uint32_t bpack(float a, float b) {
    __nv_bfloat162 t = __floats2bfloat162_rn(a, b);   // .x = a (low 16), .y = b
    return *reinterpret_cast<uint32_t*>(&t);
}

__device__ __forceinline__ void mma_bf16(float c[4], const uint32_t a[4], const uint32_t b[2]) {
    asm volatile(
        "mma.sync.aligned.m16n8k16.row.col.f32.bf16.bf16.f32 "
        "{%0,%1,%2,%3}, {%4,%5,%6,%7}, {%8,%9}, {%0,%1,%2,%3};\n"
        : "+f"(c[0]), "+f"(c[1]), "+f"(c[2]), "+f"(c[3])
        : "r"(a[0]), "r"(a[1]), "r"(a[2]), "r"(a[3]), "r"(b[0]), "r"(b[1]));
}

// ---------------- bf16x3 tensor-core GEMM: C[b] = A (MxK) * B[b] (KxN) ------
// Block tile 64x64, BK=32, 128 threads (4 warps, each 32x32 via m16n8k16).
// A/B are pre-split into bf16 hi/lo in SMEM, k-pairs packed as the 32-bit
// fragment words, so the mainloop is pure LDS + HMMA.
// MODE 0: plain store. MODE 1: batchnorm affine.
// Requires M%64==0, N%64==0, K%32==0.
template <int MODE>
__global__ void __launch_bounds__(128)
tgemm_kernel(const float* __restrict__ A,
             const float* __restrict__ B,
             float* __restrict__ C,
             int M, int N, int K,
             size_t bStrideB, size_t bStrideC,
             const float* __restrict__ gamma,
             const float* __restrict__ beta,
             const float* __restrict__ mean,
             const float* __restrict__ var)
{
    // SMEM: A_hi[64][20] A_lo[64][20] (uint32, k-pairs, pad 16->20)
    //       B_hi[16][72] B_lo[16][72] (uint32, k-pairs, pad 64->72)
    // mainloop total 19456 B; epilogue reuses as Cs[64][68] floats (17408 B)
    __shared__ uint32_t smem[4864];
    uint32_t* Ah = smem;                // 64*20 = 1280
    uint32_t* Al = smem + 1280;         // 1280
    uint32_t* Bh = smem + 2560;         // 16*72 = 1152
    uint32_t* Bl = smem + 3712;         // 1152
    float* Cs = reinterpret_cast<float*>(smem);   // [64][68] after mainloop

    const int tid  = threadIdx.x;
    const int lane = tid & 31;
    const int warp = tid >> 5;
    const int wm   = warp >> 1;
    const int wn   = warp & 1;
    const int g    = lane >> 2;
    const int tg   = lane & 3;

    const int m0 = blockIdx.y * 64;
    const int n0 = blockIdx.x * 64;
    const float* Bb = B + bStrideB * blockIdx.z;
    float*       Cb = C + bStrideC * blockIdx.z;

    float c[2][4][4] = {};

    for (int kt = 0; kt < K; kt += 32) {
        // ---- A tile: 64 rows x 32 k. float4 loads, split+pack k-pairs ----
        #pragma unroll
        for (int j = 0; j < 4; j++) {
            int lin = (tid + j * 128) * 4;
            int m = lin >> 5, k = lin & 31;
            float4 v = *(const float4*)&A[(size_t)(m0 + m) * K + kt + k];
            float h0,l0,h1,l1,h2,l2,h3,l3;
            bsplit(v.x,h0,l0); bsplit(v.y,h1,l1); bsplit(v.z,h2,l2); bsplit(v.w,h3,l3);
            int base = m * 20 + (k >> 1);
            Ah[base]     = bpack(h0, h1);
            Ah[base + 1] = bpack(h2, h3);
            Al[base]     = bpack(l0, l1);
            Al[base + 1] = bpack(l2, l3);
        }
        // ---- B tile: 32 k x 64 n. Each thread: k-pair (2kp,2kp+1), 8 n ----
        {
            int kp = tid >> 3;           // 0..15
            int nn = (tid & 7) * 8;      // 0..56
            const float* r0 = &Bb[(size_t)(kt + 2 * kp)     * N + n0 + nn];
            const float* r1 = &Bb[(size_t)(kt + 2 * kp + 1) * N + n0 + nn];
            float4 p0 = *(const float4*)r0;
            float4 p1 = *(const float4*)(r0 + 4);
            float4 q0 = *(const float4*)r1;
            float4 q1 = *(const float4*)(r1 + 4);
            const float pa[8] = {p0.x,p0.y,p0.z,p0.w,p1.x,p1.y,p1.z,p1.w};
            const float qa[8] = {q0.x,q0.y,q0.z,q0.w,q1.x,q1.y,q1.z,q1.w};
            #pragma unroll
            for (int i = 0; i < 8; i++) {
                float h0,l0,h1,l1;
                bsplit(pa[i],h0,l0); bsplit(qa[i],h1,l1);
                Bh[kp * 72 + nn + i] = bpack(h0, h1);
                Bl[kp * 72 + nn + i] = bpack(l0, l1);
            }
        }
        __syncthreads();

        #pragma unroll
        for (int ks = 0; ks < 2; ks++) {            // two k16 chunks
            const int kp0 = ks * 8;
            uint32_t ah[2][4], al[2][4], bh[4][2], bl[4][2];
            #pragma unroll
            for (int mt = 0; mt < 2; mt++) {
                int r = wm * 32 + mt * 16 + g;
                ah[mt][0] = Ah[r * 20 + kp0 + tg];
                ah[mt][1] = Ah[(r + 8) * 20 + kp0 + tg];
                ah[mt][2] = Ah[r * 20 + kp0 + tg + 4];
                ah[mt][3] = Ah[(r + 8) * 20 + kp0 + tg + 4];
                al[mt][0] = Al[r * 20 + kp0 + tg];
                al[mt][1] = Al[(r + 8) * 20 + kp0 + tg];
                al[mt][2] = Al[r * 20 + kp0 + tg + 4];
                al[mt][3] = Al[(r + 8) * 20 + kp0 + tg + 4];
            }
            #pragma unroll
            for (int nt = 0; nt < 4; nt++) {
                int col = wn * 32 + nt * 8 + g;
                bh[nt][0] = Bh[(kp0 + tg)     * 72 + col];
                bh[nt][1] = Bh[(kp0 + tg + 4) * 72 + col];
                bl[nt][0] = Bl[(kp0 + tg)     * 72 + col];
                bl[nt][1] = Bl[(kp0 + tg + 4) * 72 + col];
            }
            #pragma unroll
            for (int mt = 0; mt < 2; mt++)
                #pragma unroll
                for (int nt = 0; nt < 4; nt++) {
                    mma_bf16(c[mt][nt], ah[mt], bh[nt]);  // hi*hi
                    mma_bf16(c[mt][nt], ah[mt], bl[nt]);  // hi*lo
                    mma_bf16(c[mt][nt], al[mt], bh[nt]);  // lo*hi
                }
        }
        __syncthreads();
    }

    // ---- stage C tile to shared (stride 68) ----
    #pragma unroll
    for (int mt = 0; mt < 2; mt++)
        #pragma unroll
        for (int nt = 0; nt < 4; nt++) {
            int r   = wm * 32 + mt * 16 + g;
            int col = wn * 32 + nt * 8 + tg * 2;
            Cs[r * 68 + col]           = c[mt][nt][0];
            Cs[r * 68 + col + 1]       = c[mt][nt][1];
            Cs[(r + 8) * 68 + col]     = c[mt][nt][2];
            Cs[(r + 8) * 68 + col + 1] = c[mt][nt][3];
        }
    __syncthreads();

    // ---- write out (coalesced) ----
    #pragma unroll 8
    for (int i = tid; i < 4096; i += 128) {
        int r = i >> 6, n = i & 63;
        float v = Cs[r * 68 + n];
        if (MODE == 1) {
            int m = m0 + r;
            float sc = gamma[m] * rsqrtf(var[m] + 1e-5f);
            v = v * sc + beta[m] - mean[m] * sc;
        }
        Cb[(size_t)(m0 + r) * N + n0 + n] = v;
    }
}

// ---------------- fused p-mix + depthwise 3x3 (SAME, cross-correlation) -----
// Block: one group g (8 channels), one 2-row strip, one batch.
// Loads qkv[g*8..g*8+7] rows h0-1..h0+2, mixes to p in smem, convolves.
__global__ void __launch_bounds__(256)
pdw_kernel(const float* __restrict__ QKV,
           const float* __restrict__ Wp,
           const float* __restrict__ Wd,
           float* __restrict__ D)
{
    __shared__ float sin[8][4][WIDTH];
    __shared__ float sp [8][4][WIDTH];

    const int b  = blockIdx.z;
    const int gr = blockIdx.y;                 // group 0..23
    const int h0 = blockIdx.x * 2;             // output rows h0, h0+1
    const int tid = threadIdx.x;
    const float* src = QKV + ((size_t)b * CQKV + gr * 8) * HW;

    // load 8 in-channels x 4 rows (h0-1 .. h0+2, zero-padded)
    #pragma unroll
    for (int i = 0; i < 16; i++) {
        int lin = tid + i * 256;               // 0..4095
        int ch = lin >> 9, rs = (lin >> 7) & 3, col = lin & 127;
        int row = h0 - 1 + rs;
        sin[ch][rs][col] = ((unsigned)row < (unsigned)WIDTH)
                           ? src[ch * HW + row * WIDTH + col] : 0.f;
    }
    __syncthreads();

    // mix: p[o][r][c] = sum_i Wp[gr][o][i] * in[i][r][c]
    #pragma unroll
    for (int i = 0; i < 16; i++) {
        int lin = tid + i * 256;
        int oc = lin >> 9, rs = (lin >> 7) & 3, col = lin & 127;
        float s = 0.f;
        #pragma unroll
        for (int ic = 0; ic < 8; ic++)
            s += __ldg(&Wp[gr * 64 + oc * 8 + ic]) * sin[ic][rs][col];
        sp[oc][rs][col] = s;
    }
    __syncthreads();

    // conv: out[o][h0+hr][c], taps from sp rows hr..hr+2
    #pragma unroll
    for (int i = 0; i < 8; i++) {
        int lin = tid + i * 256;               // 0..2047
        int oc = lin >> 8, hr = (lin >> 7) & 1, col = lin & 127;
        int c = gr * 8 + oc;
        float s = 0.f;
        #pragma unroll
        for (int ky = 0; ky < 3; ky++) {
            float w0 = __ldg(&Wd[c * 9 + ky * 3 + 0]);
            float w1 = __ldg(&Wd[c * 9 + ky * 3 + 1]);
            float w2 = __ldg(&Wd[c * 9 + ky * 3 + 2]);
            const float* row = sp[oc][hr + ky];
            if (col > 0)   s += w0 * row[col - 1];
            s += w1 * row[col];
            if (col < 127) s += w2 * row[col + 1];
        }
        D[((size_t)b * CQKV + c) * HW + (h0 + hr) * WIDTH + col] = s;
    }
}

// ---------------- kv partial sums: kv[b,G] = sum_n relu(k) outer [v|1] ------
__global__ void __launch_bounds__(256)
kv_kernel(const float* __restrict__ QKV,
          const float* __restrict__ D,
          float* __restrict__ kvp)
{
    const int b = blockIdx.z, G = blockIdx.y, chunk = blockIdx.x;
    const int tid = threadIdx.x;
    const float* base = (G < 8) ? QKV + ((size_t)b * CQKV + G * 24) * HW
                                : D   + ((size_t)b * CQKV + (G - 8) * 24) * HW;
    float acc[72];
    #pragma unroll
    for (int i = 0; i < 72; i++) acc[i] = 0.f;

    #pragma unroll
    for (int it = 0; it < 4; it++) {
        int n = chunk * 2048 + it * 512 + tid * 2;
        float2 kr[8], vr[8];
        #pragma unroll
        for (int d = 0; d < 8; d++) {
            float2 t = *(const float2*)&base[(8 + d) * HW + n];
            kr[d].x = fmaxf(t.x, 0.f); kr[d].y = fmaxf(t.y, 0.f);
        }
        #pragma unroll
        for (int e = 0; e < 8; e++) vr[e] = *(const float2*)&base[(16 + e) * HW + n];
        #pragma unroll
        for (int d = 0; d < 8; d++) {
            #pragma unroll
            for (int e = 0; e < 8; e++)
                acc[d * 9 + e] += kr[d].x * vr[e].x + kr[d].y * vr[e].y;
            acc[d * 9 + 8] += kr[d].x + kr[d].y;
        }
    }

    __shared__ float red[8][72];
    const int lane = tid & 31, warp = tid >> 5;
    #pragma unroll
    for (int i = 0; i < 72; i++) {
        float v = acc[i];
        #pragma unroll
        for (int off = 16; off; off >>= 1) v += __shfl_down_sync(0xffffffffu, v, off);
        if (lane == 0) red[warp][i] = v;
    }
    __syncthreads();
    for (int i = tid; i < 72; i += 256) {
        float s = 0.f;
        #pragma unroll
        for (int w2 = 0; w2 < 8; w2++) s += red[w2][i];
        kvp[((size_t)(b * 16 + G) * 8 + chunk) * 72 + i] = s;
    }
}

__global__ void kv_reduce(const float* __restrict__ kvp, float* __restrict__ kv)
{
    int i = blockIdx.x * 256 + threadIdx.x;       // < 8*16*72 = 9216
    int bg = i / 72, j = i % 72;
    float s = 0.f;
    #pragma unroll
    for (int c = 0; c < 8; c++) s += kvp[((size_t)bg * 8 + c) * 72 + j];
    kv[i] = s;
}

// ---------------- o = normalize(relu(q) @ kv), stored channel-major ---------
__global__ void __launch_bounds__(256)
o_kernel(const float* __restrict__ QKV,
         const float* __restrict__ D,
         const float* __restrict__ kv,
         float* __restrict__ O)
{
    const int b = blockIdx.y;
    __shared__ float skv[16 * 72];
    for (int i = threadIdx.x; i < 16 * 72; i += 256) skv[i] = kv[b * 16 * 72 + i];
    __syncthreads();

    const int n = blockIdx.x * 256 + threadIdx.x;
    #pragma unroll
    for (int G = 0; G < 16; G++) {
        const float* base = (G < 8) ? QKV + ((size_t)b * CQKV + G * 24) * HW
                                    : D   + ((size_t)b * CQKV + (G - 8) * 24) * HW;
        float num[8] = {};
        float den = 0.f;
        #pragma unroll
        for (int d = 0; d < 8; d++) {
            float q = fmaxf(base[d * HW + n], 0.f);
            #pragma unroll
            for (int j = 0; j < 8; j++) num[j] += q * skv[G * 72 + d * 9 + j];
            den += q * skv[G * 72 + d * 9 + 8];
        }
        float inv = 1.f / (den + 1e-15f);
        #pragma unroll
        for (int j = 0; j < 8; j++)
            O[((size_t)b * 128 + G * 8 + j) * HW + n] = num[j] * inv;
    }
}

// ---------------- launch --------------------------------------------------
extern "C" void kernel_launch(void* const* d_in, const int* in_sizes, int n_in,
                              void* d_out, int out_size)
{
    const float* x     = (const float*)d_in[0];
    const float* W_qkv = (const float*)d_in[1];
    const float* W_p   = (const float*)d_in[2];
    const float* W_d   = (const float*)d_in[3];
    const float* W_ffn = (const float*)d_in[4];
    const float* gamma = (const float*)d_in[5];
    const float* beta  = (const float*)d_in[6];
    const float* mean  = (const float*)d_in[7];
    const float* var   = (const float*)d_in[8];
    float* out = (float*)d_out;

    float *qkv, *d, *o, *kvp, *kv;
    cudaGetSymbolAddress((void**)&qkv, g_qkv);
    cudaGetSymbolAddress((void**)&d,   g_d);
    cudaGetSymbolAddress((void**)&o,   g_o);
    cudaGetSymbolAddress((void**)&kvp, g_kvp);
    cudaGetSymbolAddress((void**)&kv,  g_kv);

    // 1) qkv = W_qkv @ x
    tgemm_kernel<0><<<dim3(HW / 64, CQKV / 64, NB), 128>>>(
        W_qkv, x, qkv, CQKV, HW, 256,
        (size_t)256 * HW, (size_t)CQKV * HW, nullptr, nullptr, nullptr, nullptr);

    // 2) d = depthwise3x3(blockdiag(W_p) @ qkv)  (fused)
    pdw_kernel<<<dim3(WIDTH / 2, 24, NB), 256>>>(qkv, W_p, W_d, d);

    // 3) kv reduction (two-stage, deterministic)
    kv_kernel<<<dim3(8, 16, NB), 256>>>(qkv, d, kvp);
    kv_reduce<<<(NB * 16 * 72) / 256, 256>>>(kvp, kv);

    // 4) o = normalize(relu(q) @ kv)
    o_kernel<<<dim3(HW / 256, NB), 256>>>(qkv, d, kv, o);

    // 5) out = BN(W_ffn @ o)
    tgemm_kernel<1><<<dim3(HW / 64, 256 / 64, NB), 128>>>(
        W_ffn, o, out, 256, HW, 128,
        (size_t)128 * HW, (size_t)256 * HW, gamma, beta, mean, var);
}